// round 17
// baseline (speedup 1.0000x reference)
#include <cuda_runtime.h>
#include <cuda_bf16.h>
#include <cstdint>

// Problem constants
#define B_ROWS   8192
#define KDIM     2304     // 48*48
#define NDIM     128      // EMB_DIM
#define TM_OWN   56       // rows OWNED per CTA (148-SM-friendly); tile computes 64
#define GRID     147      // ceil(8192/56): 146*56+16 = 8192 valid rows
#define KC       64       // K per chunk
#define NCHUNK   36       // 2304/64
#define ALPHA    0.2f
#define NTHREADS 512

// Strides in 32-bit words (bf16x2 units). Row = 64 bf16 data + 8 bf16 pad = 36 words (144B).
// ldmatrix phase reads 8 rows x 16B: row r at banks (36r)%32 + 0..3 = {4r..4r+3} -> 32 distinct.
#define SA_W 36
#define SW_W 36

// Dynamic smem layout (bytes)
#define SMA_BYTES (128 * SA_W * 4)        // 18432: 128 diff rows x (KC bf16 + pad)
#define SMW_BYTES (128 * SW_W * 4)        // 18432: 128 n-rows x (KC bf16 + pad)
#define OFF_A(s)  ((s) * SMA_BYTES)
#define OFF_W(s)  (2 * SMA_BYTES + (s) * SMW_BYTES)
#define SMEM_DYN  (2 * SMA_BYTES + 2 * SMW_BYTES)   // 73728

// W transposed to [n][k], bf16 (round-to-nearest)
__device__ __nv_bfloat16 g_wT[(size_t)NDIM * KDIM];

// Pack two floats to bf16x2 (lo = first, hi = second), round-to-nearest (unbiased).
__device__ __forceinline__ uint32_t pack_bf16x2(float lo, float hi) {
    uint32_t r;
    asm("cvt.rn.bf16x2.f32 %0, %1, %2;" : "=r"(r) : "f"(hi), "f"(lo));
    return r;
}

__device__ __forceinline__ void mma_bf16(float c[4], const uint32_t a[4],
                                         uint32_t b0, uint32_t b1) {
    asm volatile(
        "mma.sync.aligned.m16n8k16.row.col.f32.bf16.bf16.f32 "
        "{%0,%1,%2,%3}, {%4,%5,%6,%7}, {%8,%9}, {%0,%1,%2,%3};"
        : "+f"(c[0]), "+f"(c[1]), "+f"(c[2]), "+f"(c[3])
        : "r"(a[0]), "r"(a[1]), "r"(a[2]), "r"(a[3]), "r"(b0), "r"(b1));
}

__device__ __forceinline__ void ldm_x4(uint32_t r[4], uint32_t addr) {
    asm volatile("ldmatrix.sync.aligned.m8n8.x4.shared.b16 {%0,%1,%2,%3}, [%4];"
        : "=r"(r[0]), "=r"(r[1]), "=r"(r[2]), "=r"(r[3]) : "r"(addr));
}

__device__ __forceinline__ uint32_t smem_u32(const void* p) {
    uint32_t a;
    asm("{ .reg .u64 t; cvta.to.shared.u64 t, %1; cvt.u32.u64 %0, t; }" : "=r"(a) : "l"(p));
    return a;
}
__device__ __forceinline__ void cp_async16(uint32_t dst, const void* src) {
    asm volatile("cp.async.cg.shared.global [%0], [%1], 16;" :: "r"(dst), "l"(src) : "memory");
}
#define CP_COMMIT() asm volatile("cp.async.commit_group;" ::: "memory")
#define CP_WAIT0()  asm volatile("cp.async.wait_group 0;" ::: "memory")

// prep: W [k][n] fp32 -> g_wT [n][k] bf16; thread 0 also zeroes the output scalar.
__global__ void prep_w_kernel(const float* __restrict__ gW, float* __restrict__ out) {
    int i = blockIdx.x * 256 + threadIdx.x;          // over NDIM*KDIM = 294912
    if (i == 0) out[0] = 0.0f;
    int n = i / KDIM;
    int k = i - n * KDIM;
    g_wT[i] = __float2bfloat16_rn(gW[(size_t)k * NDIM + n]);   // write coalesced in k
}

__global__ __launch_bounds__(NTHREADS, 1)
void triplet_kernel(const float* __restrict__ gA,
                    const float* __restrict__ gP,
                    const float* __restrict__ gN,
                    float* __restrict__ out)
{
    extern __shared__ char sm[];
    const uint32_t sb = smem_u32(sm);

    const int t     = threadIdx.x;
    const int warp  = t >> 5;
    const int lane  = t & 31;
    const int warpM = warp & 3;    // 4 warps along M: 32 diff rows each
    const int warpN = warp >> 2;   // 4 warps along N: 32 cols each
    const int r0    = blockIdx.x * TM_OWN;

    // Accumulators: 2 m16-tiles x 4 n8-tiles x 4 regs = 32
    float acc[2][4][4];
#pragma unroll
    for (int mt = 0; mt < 2; ++mt)
#pragma unroll
        for (int nt = 0; nt < 4; ++nt)
#pragma unroll
            for (int i = 0; i < 4; ++i) acc[mt][nt][i] = 0.0f;

    // A/P/N tile: 64 rows x 16 float4 (KC=64) = 1024 items -> 2 per thread.
    // Global row clamped to B_ROWS-1 (duplicates resolve in L2; excluded by epilogue mask).
    int aRow[2], aC4[2];
    const float *pA[2], *pP[2], *pN[2];
#pragma unroll
    for (int i = 0; i < 2; ++i) {
        int idx = i * NTHREADS + t;
        aRow[i] = idx >> 4;
        aC4[i]  = idx & 15;
        int gr  = r0 + aRow[i];
        if (gr > B_ROWS - 1) gr = B_ROWS - 1;
        pA[i] = gA + (size_t)gr * KDIM + aC4[i] * 4;
        pP[i] = gP + (size_t)gr * KDIM + aC4[i] * 4;
        pN[i] = gN + (size_t)gr * KDIM + aC4[i] * 4;
    }
    // W tile cp.async: 128 n-rows x 8 16B-segs = 1024 -> 2 per thread
    int wN[2], wSeg[2];
#pragma unroll
    for (int i = 0; i < 2; ++i) {
        int idx = i * NTHREADS + t;
        wN[i]   = idx >> 3;
        wSeg[i] = idx & 7;
    }

    float4 ra[2], rp[2], rn[2];

    // ---- prologue: prefetch A(0) regs; start W(0) cp.async ----
#pragma unroll
    for (int i = 0; i < 2; ++i) {
        ra[i] = *(const float4*)(pA[i]);
        rp[i] = *(const float4*)(pP[i]);
        rn[i] = *(const float4*)(pN[i]);
    }
#pragma unroll
    for (int i = 0; i < 2; ++i)
        cp_async16(sb + OFF_W(0) + wN[i] * (SW_W * 4) + wSeg[i] * 16,
                   (const char*)g_wT + (size_t)wN[i] * (KDIM * 2) + wSeg[i] * 16);
    CP_COMMIT();

    // Per-lane ldmatrix addresses (row part); k16 adds 32B per step, stage adds OFF.
    const int lg = lane >> 3, lr = lane & 7;   // ldmatrix address group / row-in-group
    const uint32_t aRowOff[2] = {
        (uint32_t)((warpM * 32 + 0  + (lg & 1) * 8 + lr) * (SA_W * 4) + (lg >> 1) * 16),
        (uint32_t)((warpM * 32 + 16 + (lg & 1) * 8 + lr) * (SA_W * 4) + (lg >> 1) * 16)
    };
    const uint32_t bRowOff = (uint32_t)((warpN * 32 + lg * 8 + lr) * (SW_W * 4));

#pragma unroll 1
    for (int c = 0; c < NCHUNK; ++c) {
        const int s = c & 1;

        // A: STS bf16x2 diffs for chunk c (stage s free: compute(c-2) done before sync(c-1))
#pragma unroll
        for (int i = 0; i < 2; ++i) {
            uint2 ap, an;
            ap.x = pack_bf16x2(ra[i].x - rp[i].x, ra[i].y - rp[i].y);
            ap.y = pack_bf16x2(ra[i].z - rp[i].z, ra[i].w - rp[i].w);
            an.x = pack_bf16x2(ra[i].x - rn[i].x, ra[i].y - rn[i].y);
            an.y = pack_bf16x2(ra[i].z - rn[i].z, ra[i].w - rn[i].w);
            *(uint2*)(sm + OFF_A(s) + aRow[i] * (SA_W * 4) + aC4[i] * 8) = ap;
            *(uint2*)(sm + OFF_A(s) + (64 + aRow[i]) * (SA_W * 4) + aC4[i] * 8) = an;
        }

        // B: prefetch A(c+1) registers
        if (c + 1 < NCHUNK) {
            const size_t koff = (size_t)(c + 1) * KC;
#pragma unroll
            for (int i = 0; i < 2; ++i) {
                ra[i] = *(const float4*)(pA[i] + koff);
                rp[i] = *(const float4*)(pP[i] + koff);
                rn[i] = *(const float4*)(pN[i] + koff);
            }
        }

        // C: W(c) landed; D: all A(c) stores + W(c) visible to all warps
        CP_WAIT0();
        __syncthreads();

        // E: start W(c+1) into the stage vacated by compute(c-1)
        if (c + 1 < NCHUNK) {
            const char* wsrc = (const char*)g_wT + (size_t)(c + 1) * (KC * 2);
#pragma unroll
            for (int i = 0; i < 2; ++i)
                cp_async16(sb + OFF_W(1 - s) + wN[i] * (SW_W * 4) + wSeg[i] * 16,
                           wsrc + (size_t)wN[i] * (KDIM * 2) + wSeg[i] * 16);
            CP_COMMIT();
        }

        // F: compute chunk c — 4 k16-substeps, fragments via ldmatrix.x4
        const uint32_t baseA = sb + (uint32_t)OFF_A(s);
        const uint32_t baseW = sb + (uint32_t)OFF_W(s);
#pragma unroll
        for (int k16 = 0; k16 < 4; ++k16) {
            uint32_t af[2][4];
            ldm_x4(af[0], baseA + aRowOff[0] + k16 * 32);
            ldm_x4(af[1], baseA + aRowOff[1] + k16 * 32);
            uint32_t b0[4], b1[4];
            ldm_x4(b0, baseW + bRowOff + k16 * 32);        // k0-7 for nt=0..3
            ldm_x4(b1, baseW + bRowOff + k16 * 32 + 16);   // k8-15
#pragma unroll
            for (int mt = 0; mt < 2; ++mt)
#pragma unroll
                for (int nt = 0; nt < 4; ++nt)
                    mma_bf16(acc[mt][nt], af[mt], b0[nt], b1[nt]);
        }
    }

    // ---- epilogue: per-diff-row sum of squares ----
    __syncthreads();
    float* sD = (float*)sm;                 // reuse tile memory
    if (t < 128) sD[t] = 0.0f;
    __syncthreads();

#pragma unroll
    for (int mt = 0; mt < 2; ++mt) {
        int row = warpM * 32 + mt * 16 + (lane >> 2);
        float s0 = 0.0f, s1 = 0.0f;
#pragma unroll
        for (int nt = 0; nt < 4; ++nt) {
            s0 += acc[mt][nt][0] * acc[mt][nt][0] + acc[mt][nt][1] * acc[mt][nt][1];
            s1 += acc[mt][nt][2] * acc[mt][nt][2] + acc[mt][nt][3] * acc[mt][nt][3];
        }
        s0 += __shfl_xor_sync(0xffffffff, s0, 1);
        s0 += __shfl_xor_sync(0xffffffff, s0, 2);
        s1 += __shfl_xor_sync(0xffffffff, s1, 1);
        s1 += __shfl_xor_sync(0xffffffff, s1, 2);
        if ((lane & 3) == 0) {
            atomicAdd(&sD[row], s0);        // 4 warpN warps contribute per row
            atomicAdd(&sD[row + 8], s1);
        }
    }
    __syncthreads();

    if (t < 64) {
        // Owned-row mask: this CTA owns local rows [0, TM_OWN) that are in range.
        bool valid = (t < TM_OWN) && (r0 + t < B_ROWS);
        float d_ap = sD[t];                 // rows 0..63   = ap diffs
        float d_an = sD[64 + t];            // rows 64..127 = an diffs
        float loss = valid ? fmaxf(d_ap - d_an + ALPHA, 0.0f) : 0.0f;
#pragma unroll
        for (int off = 16; off > 0; off >>= 1)
            loss += __shfl_xor_sync(0xffffffff, loss, off);
        if ((t & 31) == 0)
            atomicAdd(out, loss * (1.0f / (float)B_ROWS));
    }
}

extern "C" void kernel_launch(void* const* d_in, const int* in_sizes, int n_in,
                              void* d_out, int out_size)
{
    const float* a = (const float*)d_in[0];  // batch_anchor [8192,1,48,48]
    const float* p = (const float*)d_in[1];  // batch_pos
    const float* n = (const float*)d_in[2];  // batch_neg
    const float* w = (const float*)d_in[3];  // W [2304,128]
    // d_in[4] = b: cancels in the differences; unused
    float* out = (float*)d_out;

    static bool attr_set = false;
    if (!attr_set) {
        cudaFuncSetAttribute(triplet_kernel,
                             cudaFuncAttributeMaxDynamicSharedMemorySize, SMEM_DYN);
        attr_set = true;
    }

    prep_w_kernel<<<(NDIM * KDIM) / 256, 256>>>(w, out);   // also zeroes out[0]
    triplet_kernel<<<GRID, NTHREADS, SMEM_DYN>>>(a, p, n, out);
}